// round 2
// baseline (speedup 1.0000x reference)
#include <cuda_runtime.h>

#define BATCH 8
#define CIN   64
#define HH    128
#define WW    128
#define HWSZ  (HH * WW)
#define NGRP  8
#define CG    8      // channels per group
#define OG    8      // outputs per group
#define OFFC  18
#define PH    130
#define PW    130

// Scratch (allocation-free rule: device globals)
__device__ float g_xpad[BATCH * CIN * PH * PW];   // zero-padded x for the offset conv
__device__ float g_off[BATCH * OFFC * HWSZ];      // prelu(conv(x)) offsets, [b][18][h][w]

// ---------------------------------------------------------------------------
// Kernel 1: zero-pad x into [b][c][130][130]
// ---------------------------------------------------------------------------
__global__ void pad_kernel(const float* __restrict__ x) {
    int idx = blockIdx.x * blockDim.x + threadIdx.x;
    const int total = BATCH * CIN * PH * PW;
    if (idx >= total) return;
    int xw = idx % PW;
    int t  = idx / PW;
    int yh = t % PH;
    int bc = t / PH;
    float v = 0.f;
    if (yh >= 1 && yh <= HH && xw >= 1 && xw <= WW)
        v = x[bc * HWSZ + (yh - 1) * WW + (xw - 1)];
    g_xpad[idx] = v;
}

// ---------------------------------------------------------------------------
// Kernel 2: offset conv (64ch -> 18ch, 3x3, pad 1) + PReLU
// ---------------------------------------------------------------------------
__global__ __launch_bounds__(128) void offset_conv_kernel(
    const float* __restrict__ ow, const float* __restrict__ ob,
    const float* __restrict__ pa)
{
    __shared__ __align__(16) float ws[CIN * 9 * 20];   // 46080 B

    int tx = threadIdx.x, ty = threadIdx.y;
    int tid = ty * 32 + tx;
    for (int i = tid; i < CIN * 9 * 18; i += 128) {
        int c = i / 162;
        int r = i - c * 162;
        int tap = r / 18;
        int j = r - tap * 18;
        ws[(c * 9 + tap) * 20 + j] = ow[j * (CIN * 9) + c * 9 + tap];
    }
    __syncthreads();

    int b  = blockIdx.z;
    int w0 = blockIdx.x * 32 + tx;
    int h0 = blockIdx.y * 8 + ty * 2;

    float acc[2][18];
#pragma unroll
    for (int j = 0; j < 18; j++) {
        float bj = ob[j];
        acc[0][j] = bj;
        acc[1][j] = bj;
    }

    const float* pbase = g_xpad + ((size_t)(b * CIN) * PH + h0) * PW + w0;

    for (int c = 0; c < CIN; c++) {
        const float* px = pbase + c * (PH * PW);
        float xv[4][3];
#pragma unroll
        for (int r = 0; r < 4; r++)
#pragma unroll
            for (int cc = 0; cc < 3; cc++)
                xv[r][cc] = px[r * PW + cc];

        const float* wrow = &ws[c * 180];
#pragma unroll
        for (int tap = 0; tap < 9; tap++) {
            const float4* wp = (const float4*)(wrow + tap * 20);
            float4 a0 = wp[0], a1 = wp[1], a2 = wp[2], a3 = wp[3];
            float2 a4 = *(const float2*)(wrow + tap * 20 + 16);
            float wr[18];
            wr[0]=a0.x;  wr[1]=a0.y;  wr[2]=a0.z;  wr[3]=a0.w;
            wr[4]=a1.x;  wr[5]=a1.y;  wr[6]=a1.z;  wr[7]=a1.w;
            wr[8]=a2.x;  wr[9]=a2.y;  wr[10]=a2.z; wr[11]=a2.w;
            wr[12]=a3.x; wr[13]=a3.y; wr[14]=a3.z; wr[15]=a3.w;
            wr[16]=a4.x; wr[17]=a4.y;
            int ky = tap / 3;
            int kx = tap - ky * 3;
            float x0v = xv[ky][kx];
            float x1v = xv[ky + 1][kx];
#pragma unroll
            for (int j = 0; j < 18; j++) {
                acc[0][j] += x0v * wr[j];
                acc[1][j] += x1v * wr[j];
            }
        }
    }

    float a = pa[0];
#pragma unroll
    for (int i = 0; i < 2; i++)
#pragma unroll
        for (int j = 0; j < 18; j++) {
            float v = acc[i][j];
            v = v > 0.f ? v : a * v;
            g_off[((b * OFFC + j) * HH + (h0 + i)) * WW + w0] = v;
        }
}

// ---------------------------------------------------------------------------
// Kernel 3: grouped deformable conv.
// ---------------------------------------------------------------------------
__global__ __launch_bounds__(256) void deform_kernel(
    const float* __restrict__ x, const float* __restrict__ dw,
    const float* __restrict__ db, float* __restrict__ out)
{
    __shared__ __align__(16) float s_w[NGRP * 9 * CG * OG];  // 18432 B
    __shared__ float4   s_tw[9 * WW];                        // 18432 B
    __shared__ unsigned s_to[9 * WW];                        //  4608 B

    int tx = threadIdx.x;
    int g  = threadIdx.y;
    int tid = g * 32 + tx;
    int b = blockIdx.y;
    int h = blockIdx.x;

    // stage dconv weights: s_w[g][k][c][oo]  (576 floats per group!)
    for (int i = tid; i < NGRP * 9 * CG * OG; i += 256) {
        int gg = i / 576;
        int r  = i - gg * 576;
        int k  = r >> 6;        // /64
        int rc = r & 63;
        int c  = rc >> 3;
        int oo = rc & 7;
        s_w[i] = dw[((gg * 8 + oo) * 8 + c) * 9 + k];
    }

    // per-(pixel, tap) bilinear precompute
    for (int i = tid; i < 9 * WW; i += 256) {
        int k = i >> 7;
        int w = i & 127;
        float dy = g_off[((b * OFFC + 2 * k) * HH + h) * WW + w];
        float dx = g_off[((b * OFFC + 2 * k + 1) * HH + h) * WW + w];
        int ky = k / 3 - 1;
        int kx = k - (k / 3) * 3 - 1;
        float py = (float)(h + ky) + dy;
        float px = (float)(w + kx) + dx;
        float y0f = floorf(py), x0f = floorf(px);
        float ly = py - y0f, lx = px - x0f;
        int y0 = (int)y0f, x0 = (int)x0f;
        float hy = 1.f - ly, hx = 1.f - lx;
        bool vy0 = (unsigned)y0 < (unsigned)HH;
        bool vy1 = (unsigned)(y0 + 1) < (unsigned)HH;
        bool vx0 = (unsigned)x0 < (unsigned)WW;
        bool vx1 = (unsigned)(x0 + 1) < (unsigned)WW;
        float w00 = (vy0 && vx0) ? hy * hx : 0.f;
        float w01 = (vy0 && vx1) ? hy * lx : 0.f;
        float w10 = (vy1 && vx0) ? ly * hx : 0.f;
        float w11 = (vy1 && vx1) ? ly * lx : 0.f;
        int y0c = min(max(y0, 0), HH - 1);
        int y1c = min(max(y0 + 1, 0), HH - 1);
        int x0c = min(max(x0, 0), WW - 1);
        int x1c = min(max(x0 + 1, 0), WW - 1);
        s_tw[i] = make_float4(w00, w01, w10, w11);
        s_to[i] = (unsigned)y0c | ((unsigned)x0c << 8) |
                  ((unsigned)y1c << 16) | ((unsigned)x1c << 24);
    }
    __syncthreads();

    const float* xb = x + (size_t)(b * CIN + g * CG) * HWSZ;

    float acc[4][8];
#pragma unroll
    for (int oo = 0; oo < 8; oo++) {
        float bv = db[g * 8 + oo];
        acc[0][oo] = bv; acc[1][oo] = bv; acc[2][oo] = bv; acc[3][oo] = bv;
    }

#pragma unroll 1
    for (int k = 0; k < 9; k++) {
        float4 tw[4];
        int o00[4], o01[4], o10[4], o11[4];
#pragma unroll
        for (int p = 0; p < 4; p++) {
            int wp = tx + 32 * p;
            tw[p] = s_tw[(k << 7) + wp];
            unsigned t = s_to[(k << 7) + wp];
            int y0c =  t        & 255;
            int x0c = (t >> 8)  & 255;
            int y1c = (t >> 16) & 255;
            int x1c = (t >> 24);
            o00[p] = (y0c << 7) + x0c;
            o01[p] = (y0c << 7) + x1c;
            o10[p] = (y1c << 7) + x0c;
            o11[p] = (y1c << 7) + x1c;
        }
        const float* wk = &s_w[(g * 9 + k) * 64];
#pragma unroll
        for (int c = 0; c < 8; c++) {
            float4 wa = *(const float4*)(wk + c * 8);
            float4 wb = *(const float4*)(wk + c * 8 + 4);
            const float* xc = xb + c * HWSZ;
#pragma unroll
            for (int p = 0; p < 4; p++) {
                float v = tw[p].x * xc[o00[p]] + tw[p].y * xc[o01[p]] +
                          tw[p].z * xc[o10[p]] + tw[p].w * xc[o11[p]];
                acc[p][0] += v * wa.x;
                acc[p][1] += v * wa.y;
                acc[p][2] += v * wa.z;
                acc[p][3] += v * wa.w;
                acc[p][4] += v * wb.x;
                acc[p][5] += v * wb.y;
                acc[p][6] += v * wb.z;
                acc[p][7] += v * wb.w;
            }
        }
    }

#pragma unroll
    for (int oo = 0; oo < 8; oo++)
#pragma unroll
        for (int p = 0; p < 4; p++)
            out[((b * CIN + g * 8 + oo) * HH + h) * WW + tx + 32 * p] = acc[p][oo];
}

// ---------------------------------------------------------------------------
extern "C" void kernel_launch(void* const* d_in, const int* in_sizes, int n_in,
                              void* d_out, int out_size)
{
    const float* x  = (const float*)d_in[0];
    const float* ow = (const float*)d_in[1];
    const float* ob = (const float*)d_in[2];
    const float* pa = (const float*)d_in[3];
    const float* dw = (const float*)d_in[4];
    const float* db = (const float*)d_in[5];
    float* out = (float*)d_out;

    const int totalPad = BATCH * CIN * PH * PW;
    pad_kernel<<<(totalPad + 255) / 256, 256>>>(x);
    offset_conv_kernel<<<dim3(4, 16, 8), dim3(32, 4)>>>(ow, ob, pa);
    deform_kernel<<<dim3(HH, BATCH), dim3(32, 8)>>>(x, dw, db, out);
}

// round 3
// speedup vs baseline: 1.1220x; 1.1220x over previous
#include <cuda_runtime.h>

#define BATCH 8
#define CIN   64
#define HH    128
#define WW    128
#define HWSZ  (HH * WW)
#define NGRP  8
#define CG    8
#define OG    8
#define OFFC  18

__device__ float g_off[BATCH * OFFC * HWSZ];   // prelu(conv(x)), [b][18][h][w]

// ---- packed f32x2 helpers (Blackwell) -------------------------------------
__device__ __forceinline__ unsigned long long pk2(float lo, float hi) {
    unsigned long long r;
    asm("mov.b64 %0, {%1,%2};" : "=l"(r) : "f"(lo), "f"(hi));
    return r;
}
__device__ __forceinline__ void upk2(unsigned long long v, float& lo, float& hi) {
    asm("mov.b64 {%0,%1}, %2;" : "=f"(lo), "=f"(hi) : "l"(v));
}
__device__ __forceinline__ unsigned long long ffma2(
    unsigned long long a, unsigned long long b, unsigned long long c) {
    unsigned long long d;
    asm("fma.rn.f32x2 %0, %1, %2, %3;" : "=l"(d) : "l"(a), "l"(b), "l"(c));
    return d;
}

// ---------------------------------------------------------------------------
// Kernel 1: offset conv (64ch -> 18ch, 3x3, pad 1) + PReLU, direct from x.
// Block (32,4): each thread does 2 rows x 18 outputs of a 32-wide strip.
// Accumulators packed along j-pairs -> fma.rn.f32x2 with natural 64-bit
// smem weight loads (no duplication).
// ---------------------------------------------------------------------------
__global__ __launch_bounds__(128) void offset_conv_kernel(
    const float* __restrict__ x, const float* __restrict__ ow,
    const float* __restrict__ ob, const float* __restrict__ pa)
{
    __shared__ __align__(16) float ws[CIN * 9 * 20];   // [c][tap][20], 46080 B

    int tx = threadIdx.x, ty = threadIdx.y;
    int tid = ty * 32 + tx;
    for (int i = tid; i < CIN * 9 * 18; i += 128) {
        int c = i / 162;
        int r = i - c * 162;
        int tap = r / 18;
        int j = r - tap * 18;
        ws[(c * 9 + tap) * 20 + j] = ow[j * (CIN * 9) + c * 9 + tap];
    }
    __syncthreads();

    int b  = blockIdx.z;
    int w0 = blockIdx.x * 32 + tx;
    int h0 = blockIdx.y * 8 + ty * 2;

    // loop-invariant boundary masks for the 4x3 input patch
    bool vr[4], vc[3];
#pragma unroll
    for (int r = 0; r < 4; r++) vr[r] = (unsigned)(h0 - 1 + r) < (unsigned)HH;
#pragma unroll
    for (int cc = 0; cc < 3; cc++) vc[cc] = (unsigned)(w0 - 1 + cc) < (unsigned)WW;

    unsigned long long acc2[2][9];
#pragma unroll
    for (int jj = 0; jj < 9; jj++) {
        unsigned long long t = pk2(ob[2 * jj], ob[2 * jj + 1]);
        acc2[0][jj] = t;
        acc2[1][jj] = t;
    }

    const float* xbase = x + ((size_t)(b * CIN) * HH + (h0 - 1)) * WW + (w0 - 1);

    for (int c = 0; c < CIN; c++) {
        const float* px = xbase + c * HWSZ;
        float xv[4][3];
#pragma unroll
        for (int r = 0; r < 4; r++)
#pragma unroll
            for (int cc = 0; cc < 3; cc++)
                xv[r][cc] = (vr[r] && vc[cc]) ? __ldg(px + r * WW + cc) : 0.f;

        const float* wrow = &ws[c * 180];
#pragma unroll
        for (int tap = 0; tap < 9; tap++) {
            const char* wp = (const char*)(wrow + tap * 20);
            ulonglong2 q0 = *(const ulonglong2*)(wp);
            ulonglong2 q1 = *(const ulonglong2*)(wp + 16);
            ulonglong2 q2 = *(const ulonglong2*)(wp + 32);
            ulonglong2 q3 = *(const ulonglong2*)(wp + 48);
            unsigned long long q8 = *(const unsigned long long*)(wp + 64);
            unsigned long long wj[9] = {q0.x, q0.y, q1.x, q1.y,
                                        q2.x, q2.y, q3.x, q3.y, q8};
            int ky = tap / 3;
            int kx = tap - ky * 3;
            unsigned long long a0 = pk2(xv[ky][kx],     xv[ky][kx]);
            unsigned long long a1 = pk2(xv[ky + 1][kx], xv[ky + 1][kx]);
#pragma unroll
            for (int jj = 0; jj < 9; jj++) {
                acc2[0][jj] = ffma2(a0, wj[jj], acc2[0][jj]);
                acc2[1][jj] = ffma2(a1, wj[jj], acc2[1][jj]);
            }
        }
    }

    float a = pa[0];
#pragma unroll
    for (int i = 0; i < 2; i++)
#pragma unroll
        for (int jj = 0; jj < 9; jj++) {
            float v0, v1;
            upk2(acc2[i][jj], v0, v1);
            v0 = v0 > 0.f ? v0 : a * v0;
            v1 = v1 > 0.f ? v1 : a * v1;
            int hrow = h0 + i;
            g_off[((b * OFFC + 2 * jj)     * HH + hrow) * WW + w0] = v0;
            g_off[((b * OFFC + 2 * jj + 1) * HH + hrow) * WW + w0] = v1;
        }
}

// ---------------------------------------------------------------------------
// Kernel 2: grouped deformable conv. grid (H, B); block (32 px, 8 groups).
// Phase 1: per-(pixel,tap) bilinear weights (masked) + packed clamped coords.
// Phase 2: 9 taps x 8 ch x 4 px: 4 gathers -> bilinear v -> 4 packed FMAs.
// ---------------------------------------------------------------------------
__global__ __launch_bounds__(256) void deform_kernel(
    const float* __restrict__ x, const float* __restrict__ dw,
    const float* __restrict__ db, float* __restrict__ out)
{
    __shared__ __align__(16) float s_w[NGRP * 9 * CG * OG];  // [g][k][c][oo]
    __shared__ float4   s_tw[9 * WW];
    __shared__ unsigned s_to[9 * WW];

    int tx = threadIdx.x;
    int g  = threadIdx.y;
    int tid = g * 32 + tx;
    int b = blockIdx.y;
    int h = blockIdx.x;

    for (int i = tid; i < NGRP * 9 * CG * OG; i += 256) {
        int gg = i / 576;
        int r  = i - gg * 576;
        int k  = r >> 6;
        int rc = r & 63;
        int c  = rc >> 3;
        int oo = rc & 7;
        s_w[i] = dw[((gg * 8 + oo) * 8 + c) * 9 + k];
    }

    for (int i = tid; i < 9 * WW; i += 256) {
        int k = i >> 7;
        int w = i & 127;
        float dy = g_off[((b * OFFC + 2 * k) * HH + h) * WW + w];
        float dx = g_off[((b * OFFC + 2 * k + 1) * HH + h) * WW + w];
        int ky = k / 3 - 1;
        int kx = k - (k / 3) * 3 - 1;
        float py = (float)(h + ky) + dy;
        float px = (float)(w + kx) + dx;
        float y0f = floorf(py), x0f = floorf(px);
        float ly = py - y0f, lx = px - x0f;
        int y0 = (int)y0f, x0 = (int)x0f;
        float hy = 1.f - ly, hx = 1.f - lx;
        bool vy0 = (unsigned)y0 < (unsigned)HH;
        bool vy1 = (unsigned)(y0 + 1) < (unsigned)HH;
        bool vx0 = (unsigned)x0 < (unsigned)WW;
        bool vx1 = (unsigned)(x0 + 1) < (unsigned)WW;
        float w00 = (vy0 && vx0) ? hy * hx : 0.f;
        float w01 = (vy0 && vx1) ? hy * lx : 0.f;
        float w10 = (vy1 && vx0) ? ly * hx : 0.f;
        float w11 = (vy1 && vx1) ? ly * lx : 0.f;
        int y0c = min(max(y0, 0), HH - 1);
        int y1c = min(max(y0 + 1, 0), HH - 1);
        int x0c = min(max(x0, 0), WW - 1);
        int x1c = min(max(x0 + 1, 0), WW - 1);
        s_tw[i] = make_float4(w00, w01, w10, w11);
        s_to[i] = (unsigned)y0c | ((unsigned)x0c << 8) |
                  ((unsigned)y1c << 16) | ((unsigned)x1c << 24);
    }
    __syncthreads();

    const float* xb = x + (size_t)(b * CIN + g * CG) * HWSZ;

    unsigned long long acc2[4][4];
#pragma unroll
    for (int q = 0; q < 4; q++) {
        unsigned long long t = pk2(db[g * 8 + 2 * q], db[g * 8 + 2 * q + 1]);
        acc2[0][q] = t; acc2[1][q] = t; acc2[2][q] = t; acc2[3][q] = t;
    }

#pragma unroll 1
    for (int k = 0; k < 9; k++) {
        float4 tw[4];
        int o00[4], o01[4], o10[4], o11[4];
#pragma unroll
        for (int p = 0; p < 4; p++) {
            int wp = tx + 32 * p;
            tw[p] = s_tw[(k << 7) + wp];
            unsigned t = s_to[(k << 7) + wp];
            int y0c =  t        & 255;
            int x0c = (t >> 8)  & 255;
            int y1c = (t >> 16) & 255;
            int x1c = (t >> 24);
            o00[p] = (y0c << 7) + x0c;
            o01[p] = (y0c << 7) + x1c;
            o10[p] = (y1c << 7) + x0c;
            o11[p] = (y1c << 7) + x1c;
        }
        const float* wk = &s_w[(g * 9 + k) * 64];
#pragma unroll
        for (int c = 0; c < 8; c++) {
            ulonglong2 u0 = *(const ulonglong2*)(wk + c * 8);
            ulonglong2 u1 = *(const ulonglong2*)(wk + c * 8 + 4);
            const float* xc = xb + c * HWSZ;
#pragma unroll
            for (int p = 0; p < 4; p++) {
                float v = tw[p].x * __ldg(xc + o00[p]) +
                          tw[p].y * __ldg(xc + o01[p]) +
                          tw[p].z * __ldg(xc + o10[p]) +
                          tw[p].w * __ldg(xc + o11[p]);
                unsigned long long v2 = pk2(v, v);
                acc2[p][0] = ffma2(v2, u0.x, acc2[p][0]);
                acc2[p][1] = ffma2(v2, u0.y, acc2[p][1]);
                acc2[p][2] = ffma2(v2, u1.x, acc2[p][2]);
                acc2[p][3] = ffma2(v2, u1.y, acc2[p][3]);
            }
        }
    }

#pragma unroll
    for (int q = 0; q < 4; q++)
#pragma unroll
        for (int p = 0; p < 4; p++) {
            float v0, v1;
            upk2(acc2[p][q], v0, v1);
            out[((b * CIN + g * 8 + 2 * q)     * HH + h) * WW + tx + 32 * p] = v0;
            out[((b * CIN + g * 8 + 2 * q + 1) * HH + h) * WW + tx + 32 * p] = v1;
        }
}

// ---------------------------------------------------------------------------
extern "C" void kernel_launch(void* const* d_in, const int* in_sizes, int n_in,
                              void* d_out, int out_size)
{
    const float* x  = (const float*)d_in[0];
    const float* ow = (const float*)d_in[1];
    const float* ob = (const float*)d_in[2];
    const float* pa = (const float*)d_in[3];
    const float* dw = (const float*)d_in[4];
    const float* db = (const float*)d_in[5];
    float* out = (float*)d_out;

    offset_conv_kernel<<<dim3(4, 16, 8), dim3(32, 4)>>>(x, ow, ob, pa);
    deform_kernel<<<dim3(HH, BATCH), dim3(32, 8)>>>(x, dw, db, out);
}